// round 13
// baseline (speedup 1.0000x reference)
#include <cuda_runtime.h>
#include <cuda_bf16.h>
#include <cstdint>

// ---------------- problem constants ----------------
#define N_TOK 8192
#define H_DIM 4096
#define V_DIM 32000
#define MT 128                  // token rows per CTA
#define NT 256                  // vocab cols per CTA
#define KCH 128                 // bf16 K elements per chunk (256 bytes per row)
#define NKC (H_DIM / KCH)       // 32 chunks
#define ROWB 256                // smem bytes per row (16 x 16B slots, XOR swizzle)
#define A_ST (MT * ROWB)        // 32768
#define B_ST (NT * ROWB)        // 65536
#define STB (A_ST + B_ST)       // 98304 per stage
#define NSTG 2
#define TILES_OFF 4096
#define SMEM_TOTAL (TILES_OFF + NSTG * STB)   // 200704
#define NSPLIT (V_DIM / NT)     // 125
#define SPLIT_STRIDE 128
#define IGNORE_INDEX (-100)

// ---------------- device scratch (no cudaMalloc allowed) ----------------
__device__ __align__(256) __nv_bfloat16 g_A[(size_t)N_TOK * H_DIM];    // 64 MB
__device__ __align__(256) __nv_bfloat16 g_W[(size_t)V_DIM * H_DIM];    // 256 MB
__device__ float g_pm[(size_t)N_TOK * SPLIT_STRIDE];                   // 4 MB
__device__ float g_ps[(size_t)N_TOK * SPLIT_STRIDE];                   // 4 MB
__device__ float g_tl[N_TOK];
__device__ float g_nll[N_TOK];
__device__ int   g_tgt[N_TOK];

// ---------------- helpers ----------------
__device__ __forceinline__ uint32_t smem_u32(const void* p) {
    uint32_t a;
    asm("{ .reg .u64 t; cvta.to.shared.u64 t, %1; cvt.u32.u64 %0, t; }" : "=r"(a) : "l"(p));
    return a;
}
__device__ __forceinline__ void cp16(uint32_t dst, const void* src) {
    asm volatile("cp.async.cg.shared.global [%0], [%1], 16;" :: "r"(dst), "l"(src) : "memory");
}
__device__ __forceinline__ void ldmx4(uint32_t* r, uint32_t addr) {
    asm volatile("ldmatrix.sync.aligned.m8n8.x4.shared.b16 {%0,%1,%2,%3}, [%4];"
                 : "=r"(r[0]), "=r"(r[1]), "=r"(r[2]), "=r"(r[3]) : "r"(addr));
}
__device__ __forceinline__ void mma16816(float* c, const uint32_t* a, uint32_t b0, uint32_t b1) {
    asm volatile("mma.sync.aligned.m16n8k16.row.col.f32.bf16.bf16.f32 "
                 "{%0,%1,%2,%3}, {%4,%5,%6,%7}, {%8,%9}, {%0,%1,%2,%3};"
                 : "+f"(c[0]), "+f"(c[1]), "+f"(c[2]), "+f"(c[3])
                 : "r"(a[0]), "r"(a[1]), "r"(a[2]), "r"(a[3]), "r"(b0), "r"(b1));
}

// FFMA-only exp (avoids MUFU EX2 throughput wall in the epilogue)
__device__ __forceinline__ float fastexp(float x) {
    x = fmaxf(x, -80.0f);
    float t = fmaf(x, 1.4426950408889634f, 12582912.0f);
    int ib = __float_as_int(t) << 23;
    float n = t - 12582912.0f;
    float r = fmaf(n, -0.6931471805599453f, x);
    float q = 8.3333333e-3f;
    q = fmaf(q, r, 4.1666667e-2f);
    q = fmaf(q, r, 1.6666667e-1f);
    q = fmaf(q, r, 0.5f);
    q = fmaf(q, r, 1.0f);
    q = fmaf(q, r, 1.0f);
    return __int_as_float(__float_as_int(q) + ib);
}

// ---------------- target normalization (int32 vs int64 layout probe) ----------------
__global__ void prep_targets(const int* __restrict__ w) {
    __shared__ int is64;
    if (threadIdx.x == 0) {
        int f = 1;
        for (int i = 0; i < 64; i++) {
            int hi = w[2 * i + 1];
            if (hi != 0 && hi != -1) { f = 0; break; }
        }
        is64 = f;
    }
    __syncthreads();
    int mode = is64;
    for (int i = threadIdx.x; i < N_TOK; i += blockDim.x)
        g_tgt[i] = mode ? w[2 * i] : w[i];
}

// ---------------- fp32 -> bf16 conversion ----------------
__device__ __forceinline__ void conv_body(const float* __restrict__ src, __nv_bfloat16* dst, int n4) {
    int i = blockIdx.x * blockDim.x + threadIdx.x;
    if (i < n4) {
        float4 v = ((const float4*)src)[i];
        __nv_bfloat162* d2 = (__nv_bfloat162*)dst;
        d2[2 * i]     = __floats2bfloat162_rn(v.x, v.y);
        d2[2 * i + 1] = __floats2bfloat162_rn(v.z, v.w);
    }
}
__global__ void conv_A_kernel(const float* __restrict__ src) { conv_body(src, g_A, N_TOK * H_DIM / 4); }
__global__ void conv_W_kernel(const float* __restrict__ src) { conv_body(src, g_W, (int)((size_t)V_DIM * H_DIM / 4)); }

// ---------------- fused GEMM + partial softmax ----------------
// 8 warps, 64x64 warptiles, prefetch-1 pipeline: ONE barrier per chunk, and
// next chunk's cp.asyncs are interleaved into the ks loop (issued only after
// the top barrier -> the overwritten stage is provably drained). LDSM frags
// double-buffered under 32-MMA bursts. grid (64, 125): A stays L2-resident.
__global__ void __launch_bounds__(256, 1) ce_gemm(void) {
    extern __shared__ char smem[];
    uint32_t sb = smem_u32(smem);
    uint32_t part = sb;                    // 4 KB: [row][nwid] float2 partials
    uint32_t tiles = sb + TILES_OFF;
    int tid = threadIdx.x;
    int wid = tid >> 5, lane = tid & 31;
    int mwid = wid >> 2, nwid = wid & 3;   // warp grid 2 (M) x 4 (N)
    int mt = blockIdx.x, ct = blockIdx.y;

    // cp.async bases: thread owns (row r, 16B slot cc); swizzle (cc ^ (r&7)).
    // Row advance per pass is 16 -> (r&7) invariant, so swizzle is constant.
    int r = tid >> 4, cc = tid & 15;       // 16 rows x 16 slots per pass
    const char* srcA = (const char*)(g_A + (size_t)(mt * MT + r) * H_DIM) + cc * 16;
    const char* srcB = (const char*)(g_W + (size_t)(ct * NT + r) * H_DIM) + cc * 16;
    uint32_t swz = (uint32_t)((cc ^ (r & 7)) * 16);
    uint32_t dA = tiles + (uint32_t)(r * ROWB) + swz;
    uint32_t dB = tiles + A_ST + (uint32_t)(r * ROWB) + swz;

    // full-chunk load (prologue only)
    auto load_chunk = [&](int c, int s) {
        uint32_t so = (uint32_t)(s * STB);
        size_t go = (size_t)c * (KCH * 2);
        #pragma unroll
        for (int i = 0; i < 8; i++)
            cp16(dA + so + (uint32_t)(i * 16 * ROWB),
                 srcA + go + (size_t)i * 16 * H_DIM * 2);
        #pragma unroll
        for (int i = 0; i < 16; i++)
            cp16(dB + so + (uint32_t)(i * 16 * ROWB),
                 srcB + go + (size_t)i * 16 * H_DIM * 2);
        asm volatile("cp.async.commit_group;" ::: "memory");
    };
    // quarter-chunk load: part p in 0..3 issues 2 A-passes + 4 B-passes (6 cp16)
    auto load_part = [&](int c, int s, int p) {
        uint32_t so = (uint32_t)(s * STB);
        size_t go = (size_t)c * (KCH * 2);
        #pragma unroll
        for (int j = 0; j < 2; j++) {
            int i = p * 2 + j;
            cp16(dA + so + (uint32_t)(i * 16 * ROWB),
                 srcA + go + (size_t)i * 16 * H_DIM * 2);
        }
        #pragma unroll
        for (int j = 0; j < 4; j++) {
            int i = p * 4 + j;
            cp16(dB + so + (uint32_t)(i * 16 * ROWB),
                 srcB + go + (size_t)i * 16 * H_DIM * 2);
        }
    };

    float acc[4][8][4];   // [mi 16-row][ni 8-col group][frag] = 128 regs
    #pragma unroll
    for (int a = 0; a < 4; a++)
        #pragma unroll
        for (int b = 0; b < 8; b++)
            #pragma unroll
            for (int c = 0; c < 4; c++) acc[a][b][c] = 0.0f;

    load_chunk(0, 0);   // only chunk 0 up-front; chunk 1+ stream mid-loop

    int lrow = (lane & 7) + ((lane >> 3) & 1) * 8;   // row within 16-row tile
    int halfbit = (lane >> 4) & 1;                   // 16B half of a 32B k16-step
    int xr = lrow & 7;                               // swizzle key
    uint32_t a_base0 = tiles + (uint32_t)((mwid * 64 + lrow) * ROWB);
    uint32_t b_base0 = tiles + A_ST + (uint32_t)((nwid * 64 + lrow) * ROWB);

    uint32_t af[2][4][4], br[2][4][4];   // double-buffered fragments

    auto ldf = [&](uint32_t ab, uint32_t bb, int ks, int buf) {
        uint32_t co = (uint32_t)((((ks << 1) | halfbit) ^ xr) << 4);
        #pragma unroll
        for (int mi = 0; mi < 4; mi++)
            ldmx4(af[buf][mi], ab + (uint32_t)(mi * 16 * ROWB) + co);
        #pragma unroll
        for (int g = 0; g < 4; g++)
            ldmx4(br[buf][g], bb + (uint32_t)(g * 16 * ROWB) + co);
    };

    for (int kb = 0; kb < NKC; kb++) {
        asm volatile("cp.async.wait_group 0;" ::: "memory");   // chunk kb landed
        __syncthreads();   // all warps past here => stage kb^1 fully drained

        uint32_t so = (uint32_t)((kb & 1) * STB);
        uint32_t ab = a_base0 + so;
        uint32_t bb = b_base0 + so;
        bool more = (kb + 1 < NKC);
        int nstg = (kb + 1) & 1;

        ldf(ab, bb, 0, 0);
        #pragma unroll
        for (int ks = 0; ks < 8; ks++) {       // 8 x k16 steps cover the 128-chunk
            int cur = ks & 1;
            if (ks < 7) ldf(ab, bb, ks + 1, cur ^ 1);        // prefetch frags
            if (more && ks < 4) load_part(kb + 1, nstg, ks); // stream next chunk
            #pragma unroll
            for (int mi = 0; mi < 4; mi++) {
                #pragma unroll
                for (int ni = 0; ni < 8; ni++) {
                    int g = ni >> 1, s = ni & 1;
                    mma16816(acc[mi][ni], af[cur][mi], br[cur][g][s], br[cur][g][s + 2]);
                }
            }
            if (more && ks == 4)
                asm volatile("cp.async.commit_group;" ::: "memory");
        }
    }
    __syncthreads();

    // ---- epilogue: fused partial softmax over this CTA's 128x256 logits ----
    const float NEG_INF = __int_as_float(0xff800000);
    #pragma unroll
    for (int mi = 0; mi < 4; mi++) {
        #pragma unroll
        for (int rs = 0; rs < 2; rs++) {
            int row = mwid * 64 + mi * 16 + (lane >> 2) + rs * 8;
            int token = mt * MT + row;
            int tg = g_tgt[token];
            float v[16];
            #pragma unroll
            for (int ni = 0; ni < 8; ni++) {
                v[ni * 2]     = acc[mi][ni][rs * 2];
                v[ni * 2 + 1] = acc[mi][ni][rs * 2 + 1];
            }
            // target logit capture
            #pragma unroll
            for (int ni = 0; ni < 8; ni++)
                #pragma unroll
                for (int j = 0; j < 2; j++) {
                    int gcol = ct * NT + nwid * 64 + ni * 8 + (lane & 3) * 2 + j;
                    if (gcol == tg) g_tl[token] = v[ni * 2 + j];
                }
            float m = NEG_INF;
            #pragma unroll
            for (int j = 0; j < 16; j++) m = fmaxf(m, v[j]);
            m = fmaxf(m, __shfl_xor_sync(0xffffffffu, m, 1));
            m = fmaxf(m, __shfl_xor_sync(0xffffffffu, m, 2));
            float s = 0.0f;
            #pragma unroll
            for (int j = 0; j < 16; j++) s += fastexp(v[j] - m);
            s += __shfl_xor_sync(0xffffffffu, s, 1);
            s += __shfl_xor_sync(0xffffffffu, s, 2);
            if ((lane & 3) == 0) {
                uint32_t off = part + (uint32_t)((row * 4 + nwid) * 8);
                asm volatile("st.shared.v2.f32 [%0], {%1, %2};" :: "r"(off), "f"(m), "f"(s) : "memory");
            }
        }
    }
    __syncthreads();
    if (tid < MT) {
        int row = tid;
        int token = mt * MT + row;
        float M = NEG_INF, S = 0.0f;
        #pragma unroll
        for (int w = 0; w < 4; w++) {
            float2 p;
            asm volatile("ld.shared.v2.f32 {%0, %1}, [%2];"
                         : "=f"(p.x), "=f"(p.y) : "r"(part + (uint32_t)((row * 4 + w) * 8)));
            float nm = fmaxf(M, p.x);
            S = S * fastexp(M - nm) + p.y * fastexp(p.x - nm);
            M = nm;
        }
        g_pm[(size_t)token * SPLIT_STRIDE + ct] = M;
        g_ps[(size_t)token * SPLIT_STRIDE + ct] = S;
    }
}

// ---------------- per-token logsumexp merge over 125 splits (1 warp / token) ----------------
__global__ void reduce_lse(void) {
    int warp = (blockIdx.x * blockDim.x + threadIdx.x) >> 5;
    int lane = threadIdx.x & 31;
    if (warp >= N_TOK) return;
    int token = warp;
    const float NEG_INF = __int_as_float(0xff800000);
    float lm[4], ls[4];
    #pragma unroll
    for (int i = 0; i < 4; i++) {
        int j = lane + i * 32;
        if (j < NSPLIT) {
            lm[i] = g_pm[(size_t)token * SPLIT_STRIDE + j];
            ls[i] = g_ps[(size_t)token * SPLIT_STRIDE + j];
        } else { lm[i] = NEG_INF; ls[i] = 0.0f; }
    }
    float M = NEG_INF;
    #pragma unroll
    for (int i = 0; i < 4; i++) M = fmaxf(M, lm[i]);
    #pragma unroll
    for (int o = 16; o; o >>= 1) M = fmaxf(M, __shfl_xor_sync(0xffffffffu, M, o));
    float S = 0.0f;
    #pragma unroll
    for (int i = 0; i < 4; i++) S += ls[i] * fastexp(lm[i] - M);
    #pragma unroll
    for (int o = 16; o; o >>= 1) S += __shfl_xor_sync(0xffffffffu, S, o);
    if (lane == 0) {
        int t = g_tgt[token];
        float nll = (t != IGNORE_INDEX) ? (M + logf(S) - g_tl[token]) : 0.0f;
        g_nll[token] = nll;
    }
}

// ---------------- final deterministic tree reduction ----------------
__global__ void reduce_final(float* __restrict__ out) {
    __shared__ float ss[1024];
    __shared__ int sc[1024];
    int tid = threadIdx.x;
    float s = 0.0f; int c = 0;
    for (int i = tid; i < N_TOK; i += 1024) {
        s += g_nll[i];
        c += (g_tgt[i] != IGNORE_INDEX) ? 1 : 0;
    }
    ss[tid] = s; sc[tid] = c;
    __syncthreads();
    for (int o = 512; o; o >>= 1) {
        if (tid < o) { ss[tid] += ss[tid + o]; sc[tid] += sc[tid + o]; }
        __syncthreads();
    }
    if (tid == 0) {
        int nv = sc[0] > 0 ? sc[0] : 1;
        out[0] = ss[0] / (float)nv;
    }
}

// ---------------- launch ----------------
extern "C" void kernel_launch(void* const* d_in, const int* in_sizes, int n_in,
                              void* d_out, int out_size) {
    (void)in_sizes; (void)n_in; (void)out_size;
    const float* input  = (const float*)d_in[0];
    const float* weight = (const float*)d_in[1];
    const int*   traw   = (const int*)d_in[2];
    float* out = (float*)d_out;

    prep_targets<<<1, 256>>>(traw);
    int nA4 = N_TOK * H_DIM / 4;
    int nW4 = (int)((size_t)V_DIM * H_DIM / 4);
    conv_A_kernel<<<(nA4 + 255) / 256, 256>>>(input);
    conv_W_kernel<<<(nW4 + 255) / 256, 256>>>(weight);

    cudaFuncSetAttribute(ce_gemm, cudaFuncAttributeMaxDynamicSharedMemorySize, SMEM_TOTAL);
    dim3 grid(N_TOK / MT, V_DIM / NT);   // (64, 125)
    ce_gemm<<<grid, 256, SMEM_TOTAL>>>();

    reduce_lse<<<(N_TOK * 32) / 256, 256>>>();
    reduce_final<<<1, 1024>>>(out);
}

// round 15
// speedup vs baseline: 1.0683x; 1.0683x over previous
#include <cuda_runtime.h>
#include <cuda_bf16.h>
#include <cstdint>

// ---------------- problem constants ----------------
#define N_TOK 8192
#define H_DIM 4096
#define V_DIM 32000
#define MT 128                  // token rows per CTA
#define NT 256                  // vocab cols per CTA
#define KCH 128                 // bf16 K elements per chunk (256 bytes per row)
#define NKC (H_DIM / KCH)       // 32 chunks
#define ROWB 256                // smem bytes per row (16 x 16B slots, XOR swizzle)
#define A_ST (MT * ROWB)        // 32768
#define B_ST (NT * ROWB)        // 65536
#define STB (A_ST + B_ST)       // 98304 per stage
#define NSTG 2
#define TILES_OFF 4096
#define SMEM_TOTAL (TILES_OFF + NSTG * STB)   // 200704
#define NSPLIT (V_DIM / NT)     // 125
#define SPLIT_STRIDE 128
#define IGNORE_INDEX (-100)

// ---------------- device scratch (no cudaMalloc allowed) ----------------
__device__ __align__(256) __nv_bfloat16 g_A[(size_t)N_TOK * H_DIM];    // 64 MB
__device__ __align__(256) __nv_bfloat16 g_W[(size_t)V_DIM * H_DIM];    // 256 MB
__device__ float g_pm[(size_t)N_TOK * SPLIT_STRIDE];                   // 4 MB
__device__ float g_ps[(size_t)N_TOK * SPLIT_STRIDE];                   // 4 MB
__device__ float g_tl[N_TOK];
__device__ float g_nll[N_TOK];
__device__ int   g_tgt[N_TOK];

// ---------------- helpers ----------------
__device__ __forceinline__ uint32_t smem_u32(const void* p) {
    uint32_t a;
    asm("{ .reg .u64 t; cvta.to.shared.u64 t, %1; cvt.u32.u64 %0, t; }" : "=r"(a) : "l"(p));
    return a;
}
__device__ __forceinline__ void cp16(uint32_t dst, const void* src) {
    asm volatile("cp.async.cg.shared.global [%0], [%1], 16;" :: "r"(dst), "l"(src) : "memory");
}
__device__ __forceinline__ void ldmx4(uint32_t* r, uint32_t addr) {
    asm volatile("ldmatrix.sync.aligned.m8n8.x4.shared.b16 {%0,%1,%2,%3}, [%4];"
                 : "=r"(r[0]), "=r"(r[1]), "=r"(r[2]), "=r"(r[3]) : "r"(addr));
}
__device__ __forceinline__ void mma16816(float* c, const uint32_t* a, uint32_t b0, uint32_t b1) {
    asm volatile("mma.sync.aligned.m16n8k16.row.col.f32.bf16.bf16.f32 "
                 "{%0,%1,%2,%3}, {%4,%5,%6,%7}, {%8,%9}, {%0,%1,%2,%3};"
                 : "+f"(c[0]), "+f"(c[1]), "+f"(c[2]), "+f"(c[3])
                 : "r"(a[0]), "r"(a[1]), "r"(a[2]), "r"(a[3]), "r"(b0), "r"(b1));
}

// FFMA-only exp (avoids MUFU EX2 throughput wall in the epilogue)
__device__ __forceinline__ float fastexp(float x) {
    x = fmaxf(x, -80.0f);
    float t = fmaf(x, 1.4426950408889634f, 12582912.0f);
    int ib = __float_as_int(t) << 23;
    float n = t - 12582912.0f;
    float r = fmaf(n, -0.6931471805599453f, x);
    float q = 8.3333333e-3f;
    q = fmaf(q, r, 4.1666667e-2f);
    q = fmaf(q, r, 1.6666667e-1f);
    q = fmaf(q, r, 0.5f);
    q = fmaf(q, r, 1.0f);
    q = fmaf(q, r, 1.0f);
    return __int_as_float(__float_as_int(q) + ib);
}

// ---------------- target normalization (int32 vs int64 layout probe) ----------------
__global__ void prep_targets(const int* __restrict__ w) {
    __shared__ int is64;
    if (threadIdx.x == 0) {
        int f = 1;
        for (int i = 0; i < 64; i++) {
            int hi = w[2 * i + 1];
            if (hi != 0 && hi != -1) { f = 0; break; }
        }
        is64 = f;
    }
    __syncthreads();
    int mode = is64;
    for (int i = threadIdx.x; i < N_TOK; i += blockDim.x)
        g_tgt[i] = mode ? w[2 * i] : w[i];
}

// ---------------- fp32 -> bf16 conversion ----------------
__device__ __forceinline__ void conv_body(const float* __restrict__ src, __nv_bfloat16* dst, int n4) {
    int i = blockIdx.x * blockDim.x + threadIdx.x;
    if (i < n4) {
        float4 v = ((const float4*)src)[i];
        __nv_bfloat162* d2 = (__nv_bfloat162*)dst;
        d2[2 * i]     = __floats2bfloat162_rn(v.x, v.y);
        d2[2 * i + 1] = __floats2bfloat162_rn(v.z, v.w);
    }
}
__global__ void conv_A_kernel(const float* __restrict__ src) { conv_body(src, g_A, N_TOK * H_DIM / 4); }
__global__ void conv_W_kernel(const float* __restrict__ src) { conv_body(src, g_W, (int)((size_t)V_DIM * H_DIM / 4)); }

// ---------------- fused GEMM + partial softmax ----------------
// 8 warps, 64x64 warptiles. Inner loop is FINE-GRAIN INTERLEAVED: each ks-step
// issues 8 micro-groups of [1 LDSM(next-ks frag)][optional cp.async][4 MMA],
// so LDSM floor-4 and LDGSTS rt-8 stalls are covered by the warp's own MMA
// drain instead of idling the tensor pipe (asm volatile order is preserved
// by ptxas). grid (64, 125): A stays L2-resident.
__global__ void __launch_bounds__(256, 1) ce_gemm(void) {
    extern __shared__ char smem[];
    uint32_t sb = smem_u32(smem);
    uint32_t part = sb;                    // 4 KB: [row][nwid] float2 partials
    uint32_t tiles = sb + TILES_OFF;
    int tid = threadIdx.x;
    int wid = tid >> 5, lane = tid & 31;
    int mwid = wid >> 2, nwid = wid & 3;   // warp grid 2 (M) x 4 (N)
    int mt = blockIdx.x, ct = blockIdx.y;

    // cp.async bases: thread owns (row r, 16B slot cc); swizzle (cc ^ (r&7)).
    // Row advance per pass is 16 -> (r&7) invariant, so swizzle is constant.
    int r = tid >> 4, cc = tid & 15;       // 16 rows x 16 slots per pass
    const char* srcA = (const char*)(g_A + (size_t)(mt * MT + r) * H_DIM) + cc * 16;
    const char* srcB = (const char*)(g_W + (size_t)(ct * NT + r) * H_DIM) + cc * 16;
    uint32_t swz = (uint32_t)((cc ^ (r & 7)) * 16);
    uint32_t dA = tiles + (uint32_t)(r * ROWB) + swz;
    uint32_t dB = tiles + A_ST + (uint32_t)(r * ROWB) + swz;

    // full-chunk load (prologue only)
    auto load_chunk = [&](int c, int s) {
        uint32_t so = (uint32_t)(s * STB);
        size_t go = (size_t)c * (KCH * 2);
        #pragma unroll
        for (int i = 0; i < 8; i++)
            cp16(dA + so + (uint32_t)(i * 16 * ROWB),
                 srcA + go + (size_t)i * 16 * H_DIM * 2);
        #pragma unroll
        for (int i = 0; i < 16; i++)
            cp16(dB + so + (uint32_t)(i * 16 * ROWB),
                 srcB + go + (size_t)i * 16 * H_DIM * 2);
        asm volatile("cp.async.commit_group;" ::: "memory");
    };

    float acc[4][8][4];   // [mi 16-row][ni 8-col group][frag] = 128 regs
    #pragma unroll
    for (int a = 0; a < 4; a++)
        #pragma unroll
        for (int b = 0; b < 8; b++)
            #pragma unroll
            for (int c = 0; c < 4; c++) acc[a][b][c] = 0.0f;

    load_chunk(0, 0);   // only chunk 0 up-front; chunk 1+ stream mid-loop

    int lrow = (lane & 7) + ((lane >> 3) & 1) * 8;   // row within 16-row tile
    int halfbit = (lane >> 4) & 1;                   // 16B half of a 32B k16-step
    int xr = lrow & 7;                               // swizzle key
    uint32_t a_base0 = tiles + (uint32_t)((mwid * 64 + lrow) * ROWB);
    uint32_t b_base0 = tiles + A_ST + (uint32_t)((nwid * 64 + lrow) * ROWB);

    uint32_t af[2][4][4], br[2][4][4];   // double-buffered fragments

    // burst frag load (prologue of each chunk only)
    auto ldf = [&](uint32_t ab, uint32_t bb, int ks, int buf) {
        uint32_t co = (uint32_t)((((ks << 1) | halfbit) ^ xr) << 4);
        #pragma unroll
        for (int mi = 0; mi < 4; mi++)
            ldmx4(af[buf][mi], ab + (uint32_t)(mi * 16 * ROWB) + co);
        #pragma unroll
        for (int g = 0; g < 4; g++)
            ldmx4(br[buf][g], bb + (uint32_t)(g * 16 * ROWB) + co);
    };

    for (int kb = 0; kb < NKC; kb++) {
        asm volatile("cp.async.wait_group 0;" ::: "memory");   // chunk kb landed
        __syncthreads();   // all warps past here => stage kb^1 fully drained

        uint32_t so = (uint32_t)((kb & 1) * STB);
        uint32_t ab = a_base0 + so;
        uint32_t bb = b_base0 + so;
        bool more = (kb + 1 < NKC);
        uint32_t sonx = (uint32_t)(((kb + 1) & 1) * STB);
        size_t gonx = (size_t)(kb + 1) * (KCH * 2);

        ldf(ab, bb, 0, 0);
        #pragma unroll
        for (int ks = 0; ks < 8; ks++) {       // 8 x k16 steps cover the 128-chunk
            int cur = ks & 1, nxt = cur ^ 1;
            uint32_t co = (uint32_t)(((((ks + 1) << 1) | halfbit) ^ xr) << 4);
            #pragma unroll
            for (int u = 0; u < 8; u++) {
                // 1 LDSM for next ks's fragment #u (floor hidden under MMAs below)
                if (ks < 7) {
                    if (u < 4) ldmx4(af[nxt][u], ab + (uint32_t)(u * 16 * ROWB) + co);
                    else       ldmx4(br[nxt][u - 4], bb + (uint32_t)((u - 4) * 16 * ROWB) + co);
                }
                // 4 cp.asyncs per ks, spread over ks 0..5 (24 total per chunk)
                if (more && ks < 6 && (u & 1) == 0) {
                    int idx = ks * 4 + (u >> 1);   // 0..23
                    if (idx < 8)
                        cp16(dA + sonx + (uint32_t)(idx * 16 * ROWB),
                             srcA + gonx + (size_t)idx * 16 * H_DIM * 2);
                    else
                        cp16(dB + sonx + (uint32_t)((idx - 8) * 16 * ROWB),
                             srcB + gonx + (size_t)(idx - 8) * 16 * H_DIM * 2);
                }
                // 4 MMAs of current ks (order identical to prior rounds)
                int mi = u >> 1, nb = (u & 1) * 4;
                #pragma unroll
                for (int q = 0; q < 4; q++) {
                    int ni = nb + q, g = ni >> 1, s = ni & 1;
                    mma16816(acc[mi][ni], af[cur][mi], br[cur][g][s], br[cur][g][s + 2]);
                }
            }
            if (more && ks == 5)
                asm volatile("cp.async.commit_group;" ::: "memory");
        }
    }
    __syncthreads();

    // ---- epilogue: fused partial softmax over this CTA's 128x256 logits ----
    const float NEG_INF = __int_as_float(0xff800000);
    #pragma unroll
    for (int mi = 0; mi < 4; mi++) {
        #pragma unroll
        for (int rs = 0; rs < 2; rs++) {
            int row = mwid * 64 + mi * 16 + (lane >> 2) + rs * 8;
            int token = mt * MT + row;
            int tg = g_tgt[token];
            float v[16];
            #pragma unroll
            for (int ni = 0; ni < 8; ni++) {
                v[ni * 2]     = acc[mi][ni][rs * 2];
                v[ni * 2 + 1] = acc[mi][ni][rs * 2 + 1];
            }
            // target logit capture
            #pragma unroll
            for (int ni = 0; ni < 8; ni++)
                #pragma unroll
                for (int j = 0; j < 2; j++) {
                    int gcol = ct * NT + nwid * 64 + ni * 8 + (lane & 3) * 2 + j;
                    if (gcol == tg) g_tl[token] = v[ni * 2 + j];
                }
            float m = NEG_INF;
            #pragma unroll
            for (int j = 0; j < 16; j++) m = fmaxf(m, v[j]);
            m = fmaxf(m, __shfl_xor_sync(0xffffffffu, m, 1));
            m = fmaxf(m, __shfl_xor_sync(0xffffffffu, m, 2));
            float s = 0.0f;
            #pragma unroll
            for (int j = 0; j < 16; j++) s += fastexp(v[j] - m);
            s += __shfl_xor_sync(0xffffffffu, s, 1);
            s += __shfl_xor_sync(0xffffffffu, s, 2);
            if ((lane & 3) == 0) {
                uint32_t off = part + (uint32_t)((row * 4 + nwid) * 8);
                asm volatile("st.shared.v2.f32 [%0], {%1, %2};" :: "r"(off), "f"(m), "f"(s) : "memory");
            }
        }
    }
    __syncthreads();
    if (tid < MT) {
        int row = tid;
        int token = mt * MT + row;
        float M = NEG_INF, S = 0.0f;
        #pragma unroll
        for (int w = 0; w < 4; w++) {
            float2 p;
            asm volatile("ld.shared.v2.f32 {%0, %1}, [%2];"
                         : "=f"(p.x), "=f"(p.y) : "r"(part + (uint32_t)((row * 4 + w) * 8)));
            float nm = fmaxf(M, p.x);
            S = S * fastexp(M - nm) + p.y * fastexp(p.x - nm);
            M = nm;
        }
        g_pm[(size_t)token * SPLIT_STRIDE + ct] = M;
        g_ps[(size_t)token * SPLIT_STRIDE + ct] = S;
    }
}

// ---------------- per-token logsumexp merge over 125 splits (1 warp / token) ----------------
__global__ void reduce_lse(void) {
    int warp = (blockIdx.x * blockDim.x + threadIdx.x) >> 5;
    int lane = threadIdx.x & 31;
    if (warp >= N_TOK) return;
    int token = warp;
    const float NEG_INF = __int_as_float(0xff800000);
    float lm[4], ls[4];
    #pragma unroll
    for (int i = 0; i < 4; i++) {
        int j = lane + i * 32;
        if (j < NSPLIT) {
            lm[i] = g_pm[(size_t)token * SPLIT_STRIDE + j];
            ls[i] = g_ps[(size_t)token * SPLIT_STRIDE + j];
        } else { lm[i] = NEG_INF; ls[i] = 0.0f; }
    }
    float M = NEG_INF;
    #pragma unroll
    for (int i = 0; i < 4; i++) M = fmaxf(M, lm[i]);
    #pragma unroll
    for (int o = 16; o; o >>= 1) M = fmaxf(M, __shfl_xor_sync(0xffffffffu, M, o));
    float S = 0.0f;
    #pragma unroll
    for (int i = 0; i < 4; i++) S += ls[i] * fastexp(lm[i] - M);
    #pragma unroll
    for (int o = 16; o; o >>= 1) S += __shfl_xor_sync(0xffffffffu, S, o);
    if (lane == 0) {
        int t = g_tgt[token];
        float nll = (t != IGNORE_INDEX) ? (M + logf(S) - g_tl[token]) : 0.0f;
        g_nll[token] = nll;
    }
}

// ---------------- final deterministic tree reduction ----------------
__global__ void reduce_final(float* __restrict__ out) {
    __shared__ float ss[1024];
    __shared__ int sc[1024];
    int tid = threadIdx.x;
    float s = 0.0f; int c = 0;
    for (int i = tid; i < N_TOK; i += 1024) {
        s += g_nll[i];
        c += (g_tgt[i] != IGNORE_INDEX) ? 1 : 0;
    }
    ss[tid] = s; sc[tid] = c;
    __syncthreads();
    for (int o = 512; o; o >>= 1) {
        if (tid < o) { ss[tid] += ss[tid + o]; sc[tid] += sc[tid + o]; }
        __syncthreads();
    }
    if (tid == 0) {
        int nv = sc[0] > 0 ? sc[0] : 1;
        out[0] = ss[0] / (float)nv;
    }
}

// ---------------- launch ----------------
extern "C" void kernel_launch(void* const* d_in, const int* in_sizes, int n_in,
                              void* d_out, int out_size) {
    (void)in_sizes; (void)n_in; (void)out_size;
    const float* input  = (const float*)d_in[0];
    const float* weight = (const float*)d_in[1];
    const int*   traw   = (const int*)d_in[2];
    float* out = (float*)d_out;

    prep_targets<<<1, 256>>>(traw);
    int nA4 = N_TOK * H_DIM / 4;
    int nW4 = (int)((size_t)V_DIM * H_DIM / 4);
    conv_A_kernel<<<(nA4 + 255) / 256, 256>>>(input);
    conv_W_kernel<<<(nW4 + 255) / 256, 256>>>(weight);

    cudaFuncSetAttribute(ce_gemm, cudaFuncAttributeMaxDynamicSharedMemorySize, SMEM_TOTAL);
    dim3 grid(N_TOK / MT, V_DIM / NT);   // (64, 125)
    ce_gemm<<<grid, 256, SMEM_TOTAL>>>();

    reduce_lse<<<(N_TOK * 32) / 256, 256>>>();
    reduce_final<<<1, 1024>>>(out);
}